// round 14
// baseline (speedup 1.0000x reference)
#include <cuda_runtime.h>
#include <cstdint>

#define T_STEPS 50
#define BATCH   1024
#define NIN     784
#define HID     256
#define NL      10
#define NROWS   (T_STEPS * BATCH)   // 51200

// scratch (static device arrays; no runtime allocation)
__device__ float g_wiT[NIN * HID];      // WiT[k][h] = Wi[h][k]
__device__ float g_wrT[HID * HID];      // WrT[k][h] = Wr[h][k]
__device__ float g_xw[NROWS * HID];     // XW[t*B+b][h], split-K-8 rounding
__device__ int   g_spacer_sink;

typedef unsigned long long ull;

// ---------------- packed f32x2 helpers (2 independent IEEE-rn fp32 lanes) ---
__device__ __forceinline__ ull f2_add(ull a, ull b) {
    ull r; asm("add.rn.f32x2 %0, %1, %2;" : "=l"(r) : "l"(a), "l"(b)); return r;
}

// ---------------------------------------------------------------------------
// spacer: launch-order shim. Captures land at C = 3 (mod cycle); with the
// 6-launch cycle [k0, s, s, k1, k2, s], position 3 == k1_xw.
// ---------------------------------------------------------------------------
__global__ void k_spacer() {
    if (blockIdx.x == 1u << 30) g_spacer_sink = 1;   // never taken
}

// ---------------------------------------------------------------------------
// K0: build WiT and WrT
// ---------------------------------------------------------------------------
__global__ void k0_prep(const float* __restrict__ Wi, const float* __restrict__ Wr) {
    int idx = blockIdx.x * 256 + threadIdx.x;
    if (idx < NIN * HID) {
        int k = idx >> 8;
        int h = idx & 255;
        g_wiT[idx] = Wi[h * NIN + k];
    }
    if (idx < HID * HID) {
        int k = idx >> 8;
        int h = idx & 255;
        g_wrT[idx] = Wr[h * HID + k];
    }
}

// ---------------------------------------------------------------------------
// K1: EXACT R11/R13 kernel (~385us). XW[r][h] = split-K=8 sum over
// {k : x[r][k]=1} of WiT[k][h]; weight rows via L1 LDG.128, x via __ldcs.
// 800 CTAs x 1024 threads; warp owns 2 rows; lane owns h=lane*4..+3,128+...
// ---------------------------------------------------------------------------
#define K1_THREADS 1024
#define RPW 2                        // rows per warp
#define RPC 64                       // rows per CTA (32 warps * 2)
#define KCHUNK 98
#define NCHUNK 8

__global__ __launch_bounds__(K1_THREADS) void k1_xw(const float* __restrict__ x) {
    const int tid  = threadIdx.x;
    const int lane = tid & 31;
    const int wrp  = tid >> 5;
    const int rbase = blockIdx.x * RPC + wrp * RPW;

    ull tot[RPW][4];                 // running split-K totals
#pragma unroll
    for (int r = 0; r < RPW; ++r)
#pragma unroll
        for (int j = 0; j < 4; ++j) tot[r][j] = 0ULL;

    for (int ch = 0; ch < NCHUNK; ++ch) {
        const float* wch = g_wiT + (size_t)ch * KCHUNK * HID;
#pragma unroll
        for (int r = 0; r < RPW; ++r) {
            const float* xr = x + (size_t)(rbase + r) * NIN + ch * KCHUNK;
            ull p0 = 0, p1 = 0, p2 = 0, p3 = 0;    // chunk partial
#pragma unroll
            for (int w4 = 0; w4 < 4; ++w4) {
                const bool lv = (w4 < 3) || (lane < 2);   // 98 = 3*32 + 2
                float xv = lv ? __ldcs(&xr[w4 * 32 + lane]) : 0.0f;
                unsigned m = __ballot_sync(0xffffffffu, xv != 0.0f);
                while (m) {
                    int kl = w4 * 32 + __ffs(m) - 1;
                    m &= m - 1;
                    const float* wrow = wch + kl * HID;
                    ulonglong2 wa = *(const ulonglong2*)(wrow + lane * 4);
                    ulonglong2 wb = *(const ulonglong2*)(wrow + 128 + lane * 4);
                    p0 = f2_add(p0, wa.x);
                    p1 = f2_add(p1, wa.y);
                    p2 = f2_add(p2, wb.x);
                    p3 = f2_add(p3, wb.y);
                }
            }
            tot[r][0] = f2_add(tot[r][0], p0);   // ascending chunk combine
            tot[r][1] = f2_add(tot[r][1], p1);
            tot[r][2] = f2_add(tot[r][2], p2);
            tot[r][3] = f2_add(tot[r][3], p3);
        }
    }

#pragma unroll
    for (int r = 0; r < RPW; ++r) {
        float* o = g_xw + (size_t)(rbase + r) * HID;
        *(ulonglong2*)&o[lane * 4]       = make_ulonglong2(tot[r][0], tot[r][1]);
        *(ulonglong2*)&o[128 + lane * 4] = make_ulonglong2(tot[r][2], tot[r][3]);
    }
}

// ---------------------------------------------------------------------------
// LIF elementwise update, separately rounded fp32 ops (matches reference HLO)
// ---------------------------------------------------------------------------
__device__ __forceinline__ void lif_lane(float& v, float& i, float xw, float rec,
                                         unsigned& z) {
    float vd = __fadd_rn(v, __fmul_rn(0.05f, __fadd_rn(__fsub_rn(0.0f, v), i)));
    float id = __fmul_rn(i, 0.9f);
    z = vd > 0.5f;
    v = z ? 0.0f : vd;
    i = __fadd_rn(__fadd_rn(id, xw), rec);
}

// ---------------------------------------------------------------------------
// K2 (TLP-doubled): 2 rows/CTA, 256 threads, 512 CTAs -> 4096 warps (~28/SM,
// occ ~43% vs 21%). Thread: row p = tid/128, hq = tid%128 owns h = 2hq,2hq+1
// (LDG.64 per visit; same 128B wavefront bytes as before, double the warps).
// Per-h sums are independent chains, so the h-repartition changes NOTHING
// about add order -> bit-exact. Gather = batch-4 branchless (ascending bits,
// all 4 loads issued, SEL-masked +0 folds), split-K=8 words ascending.
// ---------------------------------------------------------------------------
#define K2_ROWS 2
#define K2_THREADS 256
#define F2_ZERO 0ULL

__global__ __launch_bounds__(K2_THREADS) void k2_steps(const float* __restrict__ Wout,
                                                       const float* __restrict__ bout,
                                                       float* __restrict__ out) {
    __shared__ uint32_t s_hist[T_STEPS][K2_ROWS][8];
    __shared__ uint8_t  s_nib[K2_ROWS][128];
    __shared__ float    s_part[K2_ROWS * NL][3];

    const int tid = threadIdx.x;
    const int hq  = tid & 127;           // h pair index: owns h = 2hq, 2hq+1
    const int p   = tid >> 7;            // row within CTA (0..1)
    const int b0  = blockIdx.x * K2_ROWS;
    const int row = b0 + p;

    float2 v  = make_float2(0.f, 0.f);
    float2 cu = v;
    float2 xw_cur =
        *(const float2*)&g_xw[((size_t)(0 * BATCH + row) * HID) + hq * 2];

    for (int t = 0; t < T_STEPS; ++t) {
        float2 xw_next;
        if (t + 1 < T_STEPS)
            xw_next = *(const float2*)
                &g_xw[((size_t)((t + 1) * BATCH + row) * HID) + hq * 2];

        ull rec = 0;
        if (t > 0) {
            const uint32_t* mrow = s_hist[t - 1][p];
#pragma unroll
            for (int w8 = 0; w8 < 8; ++w8) {
                uint32_t m = mrow[w8];
                const float* wbase = g_wrT + (size_t)w8 * 32 * HID + hq * 2;
                ull pw = 0;                      // word partial
                while (m) {
                    // batch of up to 4 ascending bits; loads all issued,
                    // addends SEL-masked (+0 exact identity) -> branchless.
                    int k0 = __ffs(m) - 1;            m &= m - 1;
                    bool h1 = m != 0;
                    int k1 = h1 ? __ffs(m) - 1 : 0;   m &= m - 1;
                    bool h2 = m != 0;
                    int k2 = h2 ? __ffs(m) - 1 : 0;   m &= m - 1;
                    bool h3 = m != 0;
                    int k3 = h3 ? __ffs(m) - 1 : 0;   m &= m - 1;

                    ull w0 = *(const ull*)(wbase + (size_t)k0 * HID);
                    ull w1 = *(const ull*)(wbase + (size_t)k1 * HID);
                    ull w2 = *(const ull*)(wbase + (size_t)k2 * HID);
                    ull w3 = *(const ull*)(wbase + (size_t)k3 * HID);

                    pw = f2_add(pw, w0);
                    pw = f2_add(pw, h1 ? w1 : F2_ZERO);
                    pw = f2_add(pw, h2 ? w2 : F2_ZERO);
                    pw = f2_add(pw, h3 ? w3 : F2_ZERO);
                }
                rec = f2_add(rec, pw);           // ascending word combine
            }
        }
        float2 ra = *(float2*)&rec;

        unsigned zx, zy;
        lif_lane(v.x, cu.x, xw_cur.x, ra.x, zx);
        lif_lane(v.y, cu.y, xw_cur.y, ra.y, zy);
        s_nib[p][hq] = (uint8_t)(zx | (zy << 1));
        xw_cur = xw_next;

        __syncthreads();
        if (tid < 16) {
            int r = tid >> 3, w = tid & 7;       // word w covers hq = 16w..16w+15
            uint32_t word = 0;
#pragma unroll
            for (int j = 0; j < 16; ++j)
                word |= (uint32_t)s_nib[r][w * 16 + j] << (2 * j);
            s_hist[t][r][w] = word;
        }
        __syncthreads();
    }

    // deferred readout (no feedback; ordering perturbs only ~1e-7 relative)
    if (tid < K2_ROWS * NL * 3) {                 // 60 threads
        int pair = tid / 3, seg = tid - pair * 3;
        int g = pair / NL, l = pair - g * NL;
        int t0 = seg * 17;
        int t1 = (seg == 2) ? T_STEPS : t0 + 17;
        float s = 0.0f;
        for (int t = t0; t < t1; ++t) {
#pragma unroll
            for (int w8 = 0; w8 < 8; ++w8) {
                uint32_t m = s_hist[t][g][w8];
                while (m) {
                    int bpos = __ffs(m) - 1;
                    m &= m - 1;
                    s = __fadd_rn(s, Wout[l * HID + w8 * 32 + bpos]);
                }
            }
        }
        s_part[pair][seg] = s;
    }
    __syncthreads();
    if (tid < K2_ROWS * NL) {                     // 20 threads
        int g = tid / NL, l = tid - (tid / NL) * NL;
        float a = __fadd_rn(__fadd_rn(s_part[tid][0], s_part[tid][1]), s_part[tid][2]);
        float val = __fdiv_rn(__fadd_rn(a, __fmul_rn((float)T_STEPS, bout[l])),
                              (float)T_STEPS);
        out[(b0 + g) * NL + l] = val;
    }
}

// ---------------------------------------------------------------------------
extern "C" void kernel_launch(void* const* d_in, const int* in_sizes, int n_in,
                              void* d_out, int out_size) {
    const float* x    = (const float*)d_in[0];
    const float* Wi   = (const float*)d_in[1];
    const float* Wr   = (const float*)d_in[2];
    const float* Wout = (const float*)d_in[3];
    const float* bout = (const float*)d_in[4];
    float* out = (float*)d_out;

    // 6-launch cycle [k0, s, s, k1, k2, s]: capture position 3 == k1_xw
    k0_prep<<<(NIN * HID + 255) / 256, 256>>>(Wi, Wr);
    k_spacer<<<1, 32>>>();
    k_spacer<<<1, 32>>>();
    k1_xw<<<NROWS / RPC, K1_THREADS>>>(x);
    k2_steps<<<BATCH / K2_ROWS, K2_THREADS>>>(Wout, bout, out);
    k_spacer<<<1, 32>>>();
}

// round 15
// speedup vs baseline: 1.0634x; 1.0634x over previous
#include <cuda_runtime.h>
#include <cstdint>

#define T_STEPS 50
#define BATCH   1024
#define NIN     784
#define HID     256
#define NL      10
#define NROWS   (T_STEPS * BATCH)   // 51200

// scratch (static device arrays; no runtime allocation)
__device__ float g_wiT[NIN * HID];      // WiT[k][h] = Wi[h][k]
__device__ float g_wrT[HID * HID];      // WrT[k][h] = Wr[h][k]
__device__ float g_xw[NROWS * HID];     // XW[t*B+b][h], split-K-8 rounding
__device__ int   g_spacer_sink;

typedef unsigned long long ull;

// ---------------- packed f32x2 helpers (2 independent IEEE-rn fp32 lanes) ---
__device__ __forceinline__ ull f2_add(ull a, ull b) {
    ull r; asm("add.rn.f32x2 %0, %1, %2;" : "=l"(r) : "l"(a), "l"(b)); return r;
}

// ---------------------------------------------------------------------------
// spacer: launch-order shim. ncu capture = 0-based launch index 3, so the
// order [k0, k1, spacer, k2] profiles k2_steps this round.
// ---------------------------------------------------------------------------
__global__ void k_spacer() {
    if (blockIdx.x == 1u << 30) g_spacer_sink = 1;   // never taken
}

// ---------------------------------------------------------------------------
// K0: build WiT and WrT
// ---------------------------------------------------------------------------
__global__ void k0_prep(const float* __restrict__ Wi, const float* __restrict__ Wr) {
    int idx = blockIdx.x * 256 + threadIdx.x;
    if (idx < NIN * HID) {
        int k = idx >> 8;
        int h = idx & 255;
        g_wiT[idx] = Wi[h * NIN + k];
    }
    if (idx < HID * HID) {
        int k = idx >> 8;
        int h = idx & 255;
        g_wrT[idx] = Wr[h * HID + k];
    }
}

// ---------------------------------------------------------------------------
// K1: FROZEN (R11/R13, 408us, L1=77% ~ at the wavefront floor).
// XW[r][h] = split-K=8 sum over {k : x[r][k]=1} of WiT[k][h]; weight rows
// via L1 LDG.128, x via __ldcs. 800 CTAs x 1024 threads; warp owns 2 rows.
// ---------------------------------------------------------------------------
#define K1_THREADS 1024
#define RPW 2                        // rows per warp
#define RPC 64                       // rows per CTA (32 warps * 2)
#define KCHUNK 98
#define NCHUNK 8

__global__ __launch_bounds__(K1_THREADS) void k1_xw(const float* __restrict__ x) {
    const int tid  = threadIdx.x;
    const int lane = tid & 31;
    const int wrp  = tid >> 5;
    const int rbase = blockIdx.x * RPC + wrp * RPW;

    ull tot[RPW][4];                 // running split-K totals
#pragma unroll
    for (int r = 0; r < RPW; ++r)
#pragma unroll
        for (int j = 0; j < 4; ++j) tot[r][j] = 0ULL;

    for (int ch = 0; ch < NCHUNK; ++ch) {
        const float* wch = g_wiT + (size_t)ch * KCHUNK * HID;
#pragma unroll
        for (int r = 0; r < RPW; ++r) {
            const float* xr = x + (size_t)(rbase + r) * NIN + ch * KCHUNK;
            ull p0 = 0, p1 = 0, p2 = 0, p3 = 0;    // chunk partial
#pragma unroll
            for (int w4 = 0; w4 < 4; ++w4) {
                const bool lv = (w4 < 3) || (lane < 2);   // 98 = 3*32 + 2
                float xv = lv ? __ldcs(&xr[w4 * 32 + lane]) : 0.0f;
                unsigned m = __ballot_sync(0xffffffffu, xv != 0.0f);
                while (m) {
                    int kl = w4 * 32 + __ffs(m) - 1;
                    m &= m - 1;
                    const float* wrow = wch + kl * HID;
                    ulonglong2 wa = *(const ulonglong2*)(wrow + lane * 4);
                    ulonglong2 wb = *(const ulonglong2*)(wrow + 128 + lane * 4);
                    p0 = f2_add(p0, wa.x);
                    p1 = f2_add(p1, wa.y);
                    p2 = f2_add(p2, wb.x);
                    p3 = f2_add(p3, wb.y);
                }
            }
            tot[r][0] = f2_add(tot[r][0], p0);   // ascending chunk combine
            tot[r][1] = f2_add(tot[r][1], p1);
            tot[r][2] = f2_add(tot[r][2], p2);
            tot[r][3] = f2_add(tot[r][3], p3);
        }
    }

#pragma unroll
    for (int r = 0; r < RPW; ++r) {
        float* o = g_xw + (size_t)(rbase + r) * HID;
        *(ulonglong2*)&o[lane * 4]       = make_ulonglong2(tot[r][0], tot[r][1]);
        *(ulonglong2*)&o[128 + lane * 4] = make_ulonglong2(tot[r][2], tot[r][3]);
    }
}

// ---------------------------------------------------------------------------
// LIF elementwise update, separately rounded fp32 ops (matches reference HLO)
// ---------------------------------------------------------------------------
__device__ __forceinline__ void lif_lane(float& v, float& i, float xw, float rec,
                                         unsigned& z) {
    float vd = __fadd_rn(v, __fmul_rn(0.05f, __fadd_rn(__fsub_rn(0.0f, v), i)));
    float id = __fmul_rn(i, 0.9f);
    z = vd > 0.5f;
    v = z ? 0.0f : vd;
    i = __fadd_rn(__fadd_rn(id, xw), rec);
}

// extract up to 4 ascending set bits from m (SEL-masked validity flags)
#define TAKE4(m, k0, h1, k1, h2, k2, h3, k3)            \
    int  k0 = __ffs(m) - 1;            m &= m - 1;      \
    bool h1 = m != 0;                                   \
    int  k1 = h1 ? __ffs(m) - 1 : 0;   m &= m - 1;      \
    bool h2 = m != 0;                                   \
    int  k2 = h2 ? __ffs(m) - 1 : 0;   m &= m - 1;      \
    bool h3 = m != 0;                                   \
    int  k3 = h3 ? __ffs(m) - 1 : 0;   m &= m - 1;

// ---------------------------------------------------------------------------
// K2 (word-pair interleaved gather, MLP=8): 2 rows/CTA, 128 threads, 512
// CTAs. Thread q=tid%64 owns h[4q..4q+4) of row p=tid/64. Recurrent drive =
// split-K=8 over WrT rows from the PREVIOUS step's spike mask. Words are
// processed in PAIRS: each loop round extracts up to 4 ascending bits from
// BOTH words, issues all 8 LDG.128 (safe fallback addresses), then folds
// each word's addends into its own partial chain (SEL-masked +0 = exact
// identity). Word partials combined strictly ascending (pwa, then pwb) ->
// identical rounding sequence to R5/R13; only load scheduling changes.
// ---------------------------------------------------------------------------
#define K2_ROWS 2
#define K2_THREADS 128
#define F2_ZERO 0ULL

__global__ __launch_bounds__(K2_THREADS) void k2_steps(const float* __restrict__ Wout,
                                                       const float* __restrict__ bout,
                                                       float* __restrict__ out) {
    __shared__ uint32_t s_hist[T_STEPS][K2_ROWS][8];
    __shared__ uint8_t  s_nib[K2_ROWS][64];
    __shared__ float    s_part[K2_ROWS * NL][3];

    const int tid = threadIdx.x;
    const int q   = tid & 63;
    const int p   = tid >> 6;            // row within CTA (0..1)
    const int b0  = blockIdx.x * K2_ROWS;
    const int row = b0 + p;

    float4 v  = make_float4(0.f, 0.f, 0.f, 0.f);
    float4 cu = v;
    float4 xw_cur =
        *(const float4*)&g_xw[((size_t)(0 * BATCH + row) * HID) + q * 4];

    for (int t = 0; t < T_STEPS; ++t) {
        float4 xw_next;
        if (t + 1 < T_STEPS)
            xw_next = *(const float4*)
                &g_xw[((size_t)((t + 1) * BATCH + row) * HID) + q * 4];

        ull rec0 = 0, rec1 = 0;
        if (t > 0) {
            const uint32_t* mrow = s_hist[t - 1][p];
#pragma unroll
            for (int wp = 0; wp < 4; ++wp) {         // word pair (2wp, 2wp+1)
                uint32_t ma = mrow[2 * wp];
                uint32_t mb = mrow[2 * wp + 1];
                const float* ba = g_wrT + (size_t)(2 * wp) * 32 * HID + q * 4;
                const float* bb = g_wrT + (size_t)(2 * wp + 1) * 32 * HID + q * 4;
                ull pa0 = 0, pa1 = 0, pb0 = 0, pb1 = 0;   // word partials
                while (ma | mb) {
                    bool a0 = ma != 0;
                    bool b0v = mb != 0;
                    TAKE4(ma, ka0, a1, ka1, a2, ka2, a3, ka3)
                    TAKE4(mb, kb0, b1, kb1, b2, kb2, b3, kb3)

                    // 8 independent loads in flight
                    ulonglong2 wa0 = *(const ulonglong2*)(ba + (size_t)(a0 ? ka0 : 0) * HID);
                    ulonglong2 wa1 = *(const ulonglong2*)(ba + (size_t)ka1 * HID);
                    ulonglong2 wa2 = *(const ulonglong2*)(ba + (size_t)ka2 * HID);
                    ulonglong2 wa3 = *(const ulonglong2*)(ba + (size_t)ka3 * HID);
                    ulonglong2 wb0 = *(const ulonglong2*)(bb + (size_t)(b0v ? kb0 : 0) * HID);
                    ulonglong2 wb1 = *(const ulonglong2*)(bb + (size_t)kb1 * HID);
                    ulonglong2 wb2 = *(const ulonglong2*)(bb + (size_t)kb2 * HID);
                    ulonglong2 wb3 = *(const ulonglong2*)(bb + (size_t)kb3 * HID);

                    // fold word a (ascending bits), SEL-masked exact +0
                    pa0 = f2_add(pa0, a0 ? wa0.x : F2_ZERO);
                    pa1 = f2_add(pa1, a0 ? wa0.y : F2_ZERO);
                    pa0 = f2_add(pa0, a1 ? wa1.x : F2_ZERO);
                    pa1 = f2_add(pa1, a1 ? wa1.y : F2_ZERO);
                    pa0 = f2_add(pa0, a2 ? wa2.x : F2_ZERO);
                    pa1 = f2_add(pa1, a2 ? wa2.y : F2_ZERO);
                    pa0 = f2_add(pa0, a3 ? wa3.x : F2_ZERO);
                    pa1 = f2_add(pa1, a3 ? wa3.y : F2_ZERO);
                    // fold word b (independent chain)
                    pb0 = f2_add(pb0, b0v ? wb0.x : F2_ZERO);
                    pb1 = f2_add(pb1, b0v ? wb0.y : F2_ZERO);
                    pb0 = f2_add(pb0, b1 ? wb1.x : F2_ZERO);
                    pb1 = f2_add(pb1, b1 ? wb1.y : F2_ZERO);
                    pb0 = f2_add(pb0, b2 ? wb2.x : F2_ZERO);
                    pb1 = f2_add(pb1, b2 ? wb2.y : F2_ZERO);
                    pb0 = f2_add(pb0, b3 ? wb3.x : F2_ZERO);
                    pb1 = f2_add(pb1, b3 ? wb3.y : F2_ZERO);
                }
                rec0 = f2_add(rec0, pa0);        // ascending word combine
                rec1 = f2_add(rec1, pa1);
                rec0 = f2_add(rec0, pb0);
                rec1 = f2_add(rec1, pb1);
            }
        }
        float2 ra = *(float2*)&rec0;
        float2 rb = *(float2*)&rec1;

        unsigned zx, zy, zz, zw;
        lif_lane(v.x, cu.x, xw_cur.x, ra.x, zx);
        lif_lane(v.y, cu.y, xw_cur.y, ra.y, zy);
        lif_lane(v.z, cu.z, xw_cur.z, rb.x, zz);
        lif_lane(v.w, cu.w, xw_cur.w, rb.y, zw);
        s_nib[p][q] = (uint8_t)(zx | (zy << 1) | (zz << 2) | (zw << 3));
        xw_cur = xw_next;

        __syncthreads();
        if (tid < 16) {
            int r = tid >> 3, w = tid & 7;
            uint32_t word = 0;
#pragma unroll
            for (int j = 0; j < 8; ++j)
                word |= (uint32_t)s_nib[r][w * 8 + j] << (4 * j);
            s_hist[t][r][w] = word;
        }
        __syncthreads();
    }

    // deferred readout (no feedback; ordering perturbs only ~1e-7 relative)
    if (tid < K2_ROWS * NL * 3) {                 // 60 threads
        int pair = tid / 3, seg = tid - pair * 3;
        int g = pair / NL, l = pair - g * NL;
        int t0 = seg * 17;
        int t1 = (seg == 2) ? T_STEPS : t0 + 17;
        float s = 0.0f;
        for (int t = t0; t < t1; ++t) {
#pragma unroll
            for (int w8 = 0; w8 < 8; ++w8) {
                uint32_t m = s_hist[t][g][w8];
                while (m) {
                    int bpos = __ffs(m) - 1;
                    m &= m - 1;
                    s = __fadd_rn(s, Wout[l * HID + w8 * 32 + bpos]);
                }
            }
        }
        s_part[pair][seg] = s;
    }
    __syncthreads();
    if (tid < K2_ROWS * NL) {                     // 20 threads
        int g = tid / NL, l = tid - (tid / NL) * NL;
        float a = __fadd_rn(__fadd_rn(s_part[tid][0], s_part[tid][1]), s_part[tid][2]);
        float val = __fdiv_rn(__fadd_rn(a, __fmul_rn((float)T_STEPS, bout[l])),
                              (float)T_STEPS);
        out[(b0 + g) * NL + l] = val;
    }
}

// ---------------------------------------------------------------------------
extern "C" void kernel_launch(void* const* d_in, const int* in_sizes, int n_in,
                              void* d_out, int out_size) {
    const float* x    = (const float*)d_in[0];
    const float* Wi   = (const float*)d_in[1];
    const float* Wr   = (const float*)d_in[2];
    const float* Wout = (const float*)d_in[3];
    const float* bout = (const float*)d_in[4];
    float* out = (float*)d_out;

    // capture = 0-based launch index 3 -> profiles k2_steps
    k0_prep<<<(NIN * HID + 255) / 256, 256>>>(Wi, Wr);
    k1_xw<<<NROWS / RPC, K1_THREADS>>>(x);
    k_spacer<<<1, 32>>>();
    k2_steps<<<BATCH / K2_ROWS, K2_THREADS>>>(Wout, bout, out);
}